// round 12
// baseline (speedup 1.0000x reference)
#include <cuda_runtime.h>
#include <cuda_bf16.h>
#include <cstdint>
#include <cstddef>

// Problem dims
#define BB 8
#define TT 256
#define UU 64
#define HH 640
#define VV 1025
#define NROWS (BB*TT*UU)   // 131072
#define NPAD 1024          // GEMM covers cols 0..1023; col 1024 via GEMV in k_tanhA

// Scratch (device globals: allocation-free rule)
__device__ __nv_bfloat16 g_A[(size_t)NROWS * HH];     // tanh(enc+dec) bf16, 168MB
__device__ __nv_bfloat16 g_Wb[(size_t)NPAD * HH];     // W rows 0..1023 bf16

// ---------------------------------------------------------------------------
// Helpers
// ---------------------------------------------------------------------------
__device__ __forceinline__ uint32_t smem_u32(const void* p) {
    return (uint32_t)__cvta_generic_to_shared(p);
}
__device__ __forceinline__ void cp16(uint32_t s, const void* g) {
    asm volatile("cp.async.cg.shared.global [%0], [%1], 16;\n" :: "r"(s), "l"(g));
}
__device__ __forceinline__ void cp_commit() { asm volatile("cp.async.commit_group;\n" ::: "memory"); }
__device__ __forceinline__ void cp_wait0() { asm volatile("cp.async.wait_group 0;\n" ::: "memory"); }
__device__ __forceinline__ void cp_wait1() { asm volatile("cp.async.wait_group 1;\n" ::: "memory"); }

__device__ __forceinline__ void ldm4(uint32_t* r, uint32_t addr) {
    asm volatile("ldmatrix.sync.aligned.m8n8.x4.shared.b16 {%0,%1,%2,%3}, [%4];"
        : "=r"(r[0]), "=r"(r[1]), "=r"(r[2]), "=r"(r[3]) : "r"(addr));
}
__device__ __forceinline__ void mma16816(float* c, const uint32_t* a, const uint32_t* b) {
    asm volatile(
        "mma.sync.aligned.m16n8k16.row.col.f32.bf16.bf16.f32 "
        "{%0,%1,%2,%3}, {%4,%5,%6,%7}, {%8,%9}, {%0,%1,%2,%3};\n"
        : "+f"(c[0]), "+f"(c[1]), "+f"(c[2]), "+f"(c[3])
        : "r"(a[0]), "r"(a[1]), "r"(a[2]), "r"(a[3]), "r"(b[0]), "r"(b[1]));
}

// ---------------------------------------------------------------------------
// K0: W fp32 -> bf16 (rows 0..1023)
// ---------------------------------------------------------------------------
__global__ void k_convW(const float* __restrict__ W) {
    int i = (blockIdx.x * blockDim.x + threadIdx.x) * 2;
    if (i < NPAD * HH) {
        float2 w = *(const float2*)(W + i);
        *(__nv_bfloat162*)(g_Wb + i) = __floats2bfloat162_rn(w.x, w.y);
    }
}

// ---------------------------------------------------------------------------
// K1: A = tanh(enc+dec) -> bf16 scratch, fused GEMV for blank column 1024
// (blank logit written straight into out[row*VV+1024]; k_lsm normalizes it)
// ---------------------------------------------------------------------------
__global__ void __launch_bounds__(256) k_tanhA(
    const float* __restrict__ enc, const float* __restrict__ dec,
    const float* __restrict__ W, const float* __restrict__ bias,
    float* __restrict__ out)
{
    int warp = threadIdx.x >> 5, lane = threadIdx.x & 31;
    int row  = blockIdx.x * 8 + warp;
    int b = row >> 14;
    int t = (row >> 6) & 255;
    int u = row & 63;
    const float* e  = enc + (size_t)(b * TT + t) * HH;
    const float* d  = dec + (size_t)(b * UU + u) * HH;
    const float* wl = W + (size_t)NPAD * HH;   // W[1024,:]
    __nv_bfloat16* arow = g_A + (size_t)row * HH;

    float acc = 0.f;
#pragma unroll
    for (int j = 0; j < 10; j++) {
        int k = j * 64 + lane * 2;
        float2 ev = *(const float2*)(e + k);
        float2 dv = *(const float2*)(d + k);
        float x0 = ev.x + dv.x, x1 = ev.y + dv.y;
        float h0, h1;
        asm("tanh.approx.f32 %0, %1;" : "=f"(h0) : "f"(x0));
        asm("tanh.approx.f32 %0, %1;" : "=f"(h1) : "f"(x1));
        *(__nv_bfloat162*)(arow + k) = __floats2bfloat162_rn(h0, h1);
        float2 wv = *(const float2*)(wl + k);
        acc = fmaf(h0, wv.x, acc);
        acc = fmaf(h1, wv.y, acc);
    }
#pragma unroll
    for (int o = 16; o; o >>= 1) acc += __shfl_xor_sync(0xffffffffu, acc, o);
    if (lane == 0) out[(size_t)row * VV + 1024] = acc + bias[1024];
}

// ---------------------------------------------------------------------------
// K2: plain GEMM, ldmatrix fragment loads, BK=64, 2-stage cp.async double
// buffer with cross-sub prefetch. CTA covers rows [m0,m0+128), cols
// [n0,n0+512) as 4 sub-tiles of 128x128.
// R10 delta: __launch_bounds__(256, 2) -> 2 CTAs/SM (regs capped at 128) so
// barrier/cp-wait stalls of one CTA are hidden by the other.
// ---------------------------------------------------------------------------
#define PADE 72                 // bf16 elems per smem row (64 data + 8 pad) = 144B
#define STG_BYTES (128*PADE*2)  // 18432 per tile stage
#define MA_A0 0
#define MA_A1 STG_BYTES
#define MA_B0 (2*STG_BYTES)
#define MA_B1 (3*STG_BYTES)
#define SMEM_TOTAL (4*STG_BYTES)   // 73728 (x2 CTAs = 147456 < 228KB)

__global__ void __launch_bounds__(256, 2) k_gemm(const float* __restrict__ bias,
                                                 float* __restrict__ out)
{
    extern __shared__ char smem[];
    uint32_t sbase = smem_u32(smem);
    int tid = threadIdx.x;
    int wid = tid >> 5, lane = tid & 31;
    int gid = lane >> 2, tig = lane & 3;
    int la = lane & 7, lb = (lane >> 3) & 1, lc = (lane >> 4) & 1;
    int m0 = blockIdx.y * 128;
    int n0 = blockIdx.x * 512;

    int m_base = (wid & 3) * 32;   // 4 warps along M (32 rows each)
    int n_base = (wid >> 2) * 64;  // 2 warps along N (64 cols each)

    const uint32_t aoff[2] = {MA_A0, MA_A1};
    const uint32_t boff[2] = {MA_B0, MA_B1};

    const __nv_bfloat16* Abase = g_A + (size_t)m0 * HH;

    auto load_stage = [&](int sub, int it, int s) {
        uint32_t ab = sbase + aoff[s];
        uint32_t bb = sbase + boff[s];
        const __nv_bfloat16* Ag = Abase + it * 64;
        const __nv_bfloat16* Bg = g_Wb + (size_t)(n0 + sub * 128) * HH + it * 64;
#pragma unroll
        for (int j = 0; j < 4; j++) {      // 128 rows x 8 chunks of 16B
            int c = tid + j * 256;
            int r = c >> 3, cc = c & 7;
            cp16(ab + r * (PADE*2) + cc * 16, Ag + (size_t)r * HH + cc * 8);
        }
#pragma unroll
        for (int j = 0; j < 4; j++) {
            int c = tid + j * 256;
            int r = c >> 3, cc = c & 7;
            cp16(bb + r * (PADE*2) + cc * 16, Bg + (size_t)r * HH + cc * 8);
        }
        cp_commit();
    };

    // ldmatrix per-thread address bases (within a stage)
    uint32_t aAdd = (uint32_t)(m_base + la + lb * 8) * 144 + (uint32_t)lc * 16;
    uint32_t bAdd = (uint32_t)(n_base + la + lc * 8) * 144 + (uint32_t)lb * 16;

    load_stage(0, 0, 0);
    load_stage(0, 1, 1);

    for (int sub = 0; sub < 4; sub++) {
        float acc[2][8][4];
#pragma unroll
        for (int mt = 0; mt < 2; mt++)
#pragma unroll
            for (int nt = 0; nt < 8; nt++)
#pragma unroll
                for (int q = 0; q < 4; q++) acc[mt][nt][q] = 0.f;

        for (int kc = 0; kc < 10; kc++) {
            int s = kc & 1;
            if (sub == 3 && kc == 9) cp_wait0(); else cp_wait1();
            __syncthreads();

            uint32_t aB = sbase + aoff[s] + aAdd;
            uint32_t bB = sbase + boff[s] + bAdd;
#pragma unroll
            for (int ks = 0; ks < 4; ks++) {
                uint32_t a[2][4], b[8][2];
                ldm4(a[0], aB + ks * 32);
                ldm4(a[1], aB + 16 * 144 + ks * 32);
#pragma unroll
                for (int p = 0; p < 4; p++)
                    ldm4(&b[2 * p][0], bB + p * (16 * 144) + ks * 32);
#pragma unroll
                for (int mt = 0; mt < 2; mt++)
#pragma unroll
                    for (int nt = 0; nt < 8; nt++)
                        mma16816(acc[mt][nt], a[mt], b[nt]);
            }
            __syncthreads();
            if (kc + 2 < 10)      load_stage(sub, kc + 2, s);
            else if (sub < 3)     load_stage(sub + 1, kc + 2 - 10, s);
        }

        // ---- epilogue: bias add + store logits
#pragma unroll
        for (int mt = 0; mt < 2; mt++) {
#pragma unroll
            for (int nt = 0; nt < 8; nt++) {
                int row = m0 + m_base + mt * 16 + gid;
                int col = n0 + sub * 128 + n_base + nt * 8 + tig * 2;
                float2 bi = *(const float2*)(bias + col);
                float* p0 = out + (size_t)row * VV + col;
                p0[0] = acc[mt][nt][0] + bi.x;
                p0[1] = acc[mt][nt][1] + bi.y;
                float* p1 = out + (size_t)(row + 8) * VV + col;
                p1[0] = acc[mt][nt][2] + bi.x;
                p1[1] = acc[mt][nt][3] + bi.y;
            }
        }
    }
}

// ---------------------------------------------------------------------------
// K3: in-place log_softmax over last dim (V=1025).
// Warp-per-row: barrier-free, shfl-only reductions, fully-coalesced loads.
// ---------------------------------------------------------------------------
__global__ void __launch_bounds__(256) k_lsm(float* __restrict__ out) {
    int warp = threadIdx.x >> 5, lane = threadIdx.x & 31;
    int row = blockIdx.x * 8 + warp;
    float* p = out + (size_t)row * VV;

    float v[32];
#pragma unroll
    for (int j = 0; j < 32; j++) v[j] = p[lane + j * 32];
    float vb = (lane == 0) ? p[1024] : -1e30f;

    float mx = vb;
#pragma unroll
    for (int j = 0; j < 32; j++) mx = fmaxf(mx, v[j]);
#pragma unroll
    for (int o = 16; o; o >>= 1) mx = fmaxf(mx, __shfl_xor_sync(0xffffffffu, mx, o));

    float s = (lane == 0) ? __expf(vb - mx) : 0.f;
#pragma unroll
    for (int j = 0; j < 32; j++) s += __expf(v[j] - mx);
#pragma unroll
    for (int o = 16; o; o >>= 1) s += __shfl_xor_sync(0xffffffffu, s, o);

    float lse = mx + __logf(s);

#pragma unroll
    for (int j = 0; j < 32; j++) p[lane + j * 32] = v[j] - lse;
    if (lane == 0) p[1024] = vb - lse;
}

// ---------------------------------------------------------------------------
extern "C" void kernel_launch(void* const* d_in, const int* in_sizes, int n_in,
                              void* d_out, int out_size) {
    (void)in_sizes; (void)n_in; (void)out_size;
    const float* enc  = (const float*)d_in[0];
    const float* dec  = (const float*)d_in[1];
    const float* W    = (const float*)d_in[2];
    const float* bias = (const float*)d_in[3];
    float* out = (float*)d_out;

    k_convW<<<(NPAD * HH / 2 + 255) / 256, 256>>>(W);
    k_tanhA<<<NROWS / 8, 256>>>(enc, dec, W, bias, out);

    cudaFuncSetAttribute(k_gemm, cudaFuncAttributeMaxDynamicSharedMemorySize, SMEM_TOTAL);
    dim3 grid(NPAD / 512, NROWS / 128);   // (2, 1024)
    k_gemm<<<grid, 256, SMEM_TOTAL>>>(bias, out);

    k_lsm<<<NROWS / 8, 256>>>(out);
}

// round 14
// speedup vs baseline: 1.0176x; 1.0176x over previous
#include <cuda_runtime.h>
#include <cuda_bf16.h>
#include <cstdint>
#include <cstddef>

// Problem dims
#define BB 8
#define TT 256
#define UU 64
#define HH 640
#define VV 1025
#define NROWS (BB*TT*UU)   // 131072
#define NPAD 1024          // GEMM covers cols 0..1023; col 1024 via GEMV in k_tanhA

// Scratch (device globals: allocation-free rule)
__device__ __nv_bfloat16 g_A[(size_t)NROWS * HH];     // tanh(enc+dec) bf16, 168MB
__device__ __nv_bfloat16 g_Wb[(size_t)NPAD * HH];     // W rows 0..1023 bf16

// ---------------------------------------------------------------------------
// Helpers
// ---------------------------------------------------------------------------
__device__ __forceinline__ uint32_t smem_u32(const void* p) {
    return (uint32_t)__cvta_generic_to_shared(p);
}
__device__ __forceinline__ void cp16(uint32_t s, const void* g) {
    asm volatile("cp.async.cg.shared.global [%0], [%1], 16;\n" :: "r"(s), "l"(g));
}
__device__ __forceinline__ void cp_commit() { asm volatile("cp.async.commit_group;\n" ::: "memory"); }
__device__ __forceinline__ void cp_wait0() { asm volatile("cp.async.wait_group 0;\n" ::: "memory"); }
__device__ __forceinline__ void cp_wait1() { asm volatile("cp.async.wait_group 1;\n" ::: "memory"); }

__device__ __forceinline__ void ldm4(uint32_t* r, uint32_t addr) {
    asm volatile("ldmatrix.sync.aligned.m8n8.x4.shared.b16 {%0,%1,%2,%3}, [%4];"
        : "=r"(r[0]), "=r"(r[1]), "=r"(r[2]), "=r"(r[3]) : "r"(addr));
}
__device__ __forceinline__ void mma16816(float* c, const uint32_t* a, const uint32_t* b) {
    asm volatile(
        "mma.sync.aligned.m16n8k16.row.col.f32.bf16.bf16.f32 "
        "{%0,%1,%2,%3}, {%4,%5,%6,%7}, {%8,%9}, {%0,%1,%2,%3};\n"
        : "+f"(c[0]), "+f"(c[1]), "+f"(c[2]), "+f"(c[3])
        : "r"(a[0]), "r"(a[1]), "r"(a[2]), "r"(a[3]), "r"(b[0]), "r"(b[1]));
}

// ---------------------------------------------------------------------------
// K0: W fp32 -> bf16 (rows 0..1023)
// ---------------------------------------------------------------------------
__global__ void k_convW(const float* __restrict__ W) {
    int i = (blockIdx.x * blockDim.x + threadIdx.x) * 2;
    if (i < NPAD * HH) {
        float2 w = *(const float2*)(W + i);
        *(__nv_bfloat162*)(g_Wb + i) = __floats2bfloat162_rn(w.x, w.y);
    }
}

// ---------------------------------------------------------------------------
// K1: A = tanh(enc+dec) -> bf16 scratch, fused GEMV for blank column 1024
// (blank logit written straight into out[row*VV+1024]; k_lsm normalizes it)
// ---------------------------------------------------------------------------
__global__ void __launch_bounds__(256) k_tanhA(
    const float* __restrict__ enc, const float* __restrict__ dec,
    const float* __restrict__ W, const float* __restrict__ bias,
    float* __restrict__ out)
{
    int warp = threadIdx.x >> 5, lane = threadIdx.x & 31;
    int row  = blockIdx.x * 8 + warp;
    int b = row >> 14;
    int t = (row >> 6) & 255;
    int u = row & 63;
    const float* e  = enc + (size_t)(b * TT + t) * HH;
    const float* d  = dec + (size_t)(b * UU + u) * HH;
    const float* wl = W + (size_t)NPAD * HH;   // W[1024,:]
    __nv_bfloat16* arow = g_A + (size_t)row * HH;

    float acc = 0.f;
#pragma unroll
    for (int j = 0; j < 10; j++) {
        int k = j * 64 + lane * 2;
        float2 ev = *(const float2*)(e + k);
        float2 dv = *(const float2*)(d + k);
        float x0 = ev.x + dv.x, x1 = ev.y + dv.y;
        float h0, h1;
        asm("tanh.approx.f32 %0, %1;" : "=f"(h0) : "f"(x0));
        asm("tanh.approx.f32 %0, %1;" : "=f"(h1) : "f"(x1));
        *(__nv_bfloat162*)(arow + k) = __floats2bfloat162_rn(h0, h1);
        float2 wv = *(const float2*)(wl + k);
        acc = fmaf(h0, wv.x, acc);
        acc = fmaf(h1, wv.y, acc);
    }
#pragma unroll
    for (int o = 16; o; o >>= 1) acc += __shfl_xor_sync(0xffffffffu, acc, o);
    if (lane == 0) out[(size_t)row * VV + 1024] = acc + bias[1024];
}

// ---------------------------------------------------------------------------
// K2: GEMM: 4 warps/CTA (128 thr), warp grid 2Mx2N, warp tile 64x64
// (128 fp32 acc/thread). Smem read redundancy A x2 + B x2 (64KB/kc vs
// 96KB/kc at 8 warps) and LDSM-per-MMA down 33%. HMMA count unchanged.
// 2 CTAs/SM by regs (<=256) + smem (2x73.7KB<228KB) -> 8 warps/SM kept.
// CTA covers rows [m0,m0+128), cols [n0,n0+512) as 4 sub-tiles of 128x128.
// BK=64, 2-stage cp.async double buffer with cross-sub prefetch.
// Launched twice (noff = 0, 512) to double ncu sampling odds on this kernel.
// ---------------------------------------------------------------------------
#define PADE 72                 // bf16 elems per smem row (64 data + 8 pad) = 144B
#define STG_BYTES (128*PADE*2)  // 18432 per tile stage
#define MA_A0 0
#define MA_A1 STG_BYTES
#define MA_B0 (2*STG_BYTES)
#define MA_B1 (3*STG_BYTES)
#define SMEM_TOTAL (4*STG_BYTES)   // 73728 (x2 CTAs = 147456 < 228KB)

__global__ void __launch_bounds__(128, 2) k_gemm(const float* __restrict__ bias,
                                                 float* __restrict__ out,
                                                 int noff)
{
    extern __shared__ char smem[];
    uint32_t sbase = smem_u32(smem);
    int tid = threadIdx.x;
    int wid = tid >> 5, lane = tid & 31;
    int gid = lane >> 2, tig = lane & 3;
    int la = lane & 7, lb = (lane >> 3) & 1, lc = (lane >> 4) & 1;
    int m0 = blockIdx.y * 128;
    int n0 = noff;

    int m_base = (wid & 1) * 64;   // 2 warps along M (64 rows each)
    int n_base = (wid >> 1) * 64;  // 2 warps along N (64 cols each)

    const uint32_t aoff[2] = {MA_A0, MA_A1};
    const uint32_t boff[2] = {MA_B0, MA_B1};

    const __nv_bfloat16* Abase = g_A + (size_t)m0 * HH;

    auto load_stage = [&](int sub, int it, int s) {
        uint32_t ab = sbase + aoff[s];
        uint32_t bb = sbase + boff[s];
        const __nv_bfloat16* Ag = Abase + it * 64;
        const __nv_bfloat16* Bg = g_Wb + (size_t)(n0 + sub * 128) * HH + it * 64;
#pragma unroll
        for (int j = 0; j < 8; j++) {      // 128 rows x 8 chunks of 16B
            int c = tid + j * 128;
            int r = c >> 3, cc = c & 7;
            cp16(ab + r * (PADE*2) + cc * 16, Ag + (size_t)r * HH + cc * 8);
        }
#pragma unroll
        for (int j = 0; j < 8; j++) {
            int c = tid + j * 128;
            int r = c >> 3, cc = c & 7;
            cp16(bb + r * (PADE*2) + cc * 16, Bg + (size_t)r * HH + cc * 8);
        }
        cp_commit();
    };

    // ldmatrix per-thread address bases (within a stage)
    uint32_t aAdd = (uint32_t)(m_base + la + lb * 8) * 144 + (uint32_t)lc * 16;
    uint32_t bAdd = (uint32_t)(n_base + la + lc * 8) * 144 + (uint32_t)lb * 16;

    load_stage(0, 0, 0);
    load_stage(0, 1, 1);

    for (int sub = 0; sub < 4; sub++) {
        float acc[4][8][4];
#pragma unroll
        for (int mt = 0; mt < 4; mt++)
#pragma unroll
            for (int nt = 0; nt < 8; nt++)
#pragma unroll
                for (int q = 0; q < 4; q++) acc[mt][nt][q] = 0.f;

        for (int kc = 0; kc < 10; kc++) {
            int s = kc & 1;
            if (sub == 3 && kc == 9) cp_wait0(); else cp_wait1();
            __syncthreads();

            uint32_t aB = sbase + aoff[s] + aAdd;
            uint32_t bB = sbase + boff[s] + bAdd;
#pragma unroll
            for (int ks = 0; ks < 4; ks++) {
                uint32_t a[4][4], b[8][2];
#pragma unroll
                for (int mt = 0; mt < 4; mt++)
                    ldm4(a[mt], aB + mt * (16 * 144) + ks * 32);
#pragma unroll
                for (int p = 0; p < 4; p++)
                    ldm4(&b[2 * p][0], bB + p * (16 * 144) + ks * 32);
#pragma unroll
                for (int mt = 0; mt < 4; mt++)
#pragma unroll
                    for (int nt = 0; nt < 8; nt++)
                        mma16816(acc[mt][nt], a[mt], b[nt]);
            }
            __syncthreads();
            if (kc + 2 < 10)      load_stage(sub, kc + 2, s);
            else if (sub < 3)     load_stage(sub + 1, kc + 2 - 10, s);
        }

        // ---- epilogue: bias add + store logits
#pragma unroll
        for (int mt = 0; mt < 4; mt++) {
#pragma unroll
            for (int nt = 0; nt < 8; nt++) {
                int row = m0 + m_base + mt * 16 + gid;
                int col = n0 + sub * 128 + n_base + nt * 8 + tig * 2;
                float2 bi = *(const float2*)(bias + col);
                float* p0 = out + (size_t)row * VV + col;
                p0[0] = acc[mt][nt][0] + bi.x;
                p0[1] = acc[mt][nt][1] + bi.y;
                float* p1 = out + (size_t)(row + 8) * VV + col;
                p1[0] = acc[mt][nt][2] + bi.x;
                p1[1] = acc[mt][nt][3] + bi.y;
            }
        }
    }
}

// ---------------------------------------------------------------------------
// K3: in-place log_softmax over last dim (V=1025).
// Warp-per-row: barrier-free, shfl-only reductions, fully-coalesced loads.
// ---------------------------------------------------------------------------
__global__ void __launch_bounds__(256) k_lsm(float* __restrict__ out) {
    int warp = threadIdx.x >> 5, lane = threadIdx.x & 31;
    int row = blockIdx.x * 8 + warp;
    float* p = out + (size_t)row * VV;

    float v[32];
#pragma unroll
    for (int j = 0; j < 32; j++) v[j] = p[lane + j * 32];
    float vb = (lane == 0) ? p[1024] : -1e30f;

    float mx = vb;
#pragma unroll
    for (int j = 0; j < 32; j++) mx = fmaxf(mx, v[j]);
#pragma unroll
    for (int o = 16; o; o >>= 1) mx = fmaxf(mx, __shfl_xor_sync(0xffffffffu, mx, o));

    float s = (lane == 0) ? __expf(vb - mx) : 0.f;
#pragma unroll
    for (int j = 0; j < 32; j++) s += __expf(v[j] - mx);
#pragma unroll
    for (int o = 16; o; o >>= 1) s += __shfl_xor_sync(0xffffffffu, s, o);

    float lse = mx + __logf(s);

#pragma unroll
    for (int j = 0; j < 32; j++) p[lane + j * 32] = v[j] - lse;
    if (lane == 0) p[1024] = vb - lse;
}

// ---------------------------------------------------------------------------
extern "C" void kernel_launch(void* const* d_in, const int* in_sizes, int n_in,
                              void* d_out, int out_size) {
    (void)in_sizes; (void)n_in; (void)out_size;
    const float* enc  = (const float*)d_in[0];
    const float* dec  = (const float*)d_in[1];
    const float* W    = (const float*)d_in[2];
    const float* bias = (const float*)d_in[3];
    float* out = (float*)d_out;

    k_convW<<<(NPAD * HH / 2 + 255) / 256, 256>>>(W);
    k_tanhA<<<NROWS / 8, 256>>>(enc, dec, W, bias, out);

    cudaFuncSetAttribute(k_gemm, cudaFuncAttributeMaxDynamicSharedMemorySize, SMEM_TOTAL);
    dim3 grid(1, NROWS / 128);   // 1024 CTAs per N-half
    k_gemm<<<grid, 128, SMEM_TOTAL>>>(bias, out, 0);
    k_gemm<<<grid, 128, SMEM_TOTAL>>>(bias, out, 512);

    k_lsm<<<NROWS / 8, 256>>>(out);
}

// round 15
// speedup vs baseline: 1.0644x; 1.0459x over previous
#include <cuda_runtime.h>
#include <cuda_bf16.h>
#include <cstdint>
#include <cstddef>

// Problem dims
#define BB 8
#define TT 256
#define UU 64
#define HH 640
#define VV 1025
#define NROWS (BB*TT*UU)   // 131072
#define NPAD 1024          // GEMM covers cols 0..1023; col 1024 via GEMV in k_tanhA

// Scratch (device globals: allocation-free rule)
__device__ __nv_bfloat16 g_A[(size_t)NROWS * HH];     // tanh(enc+dec) bf16, 168MB
__device__ __nv_bfloat16 g_Wb[(size_t)NPAD * HH];     // W rows 0..1023 bf16

// ---------------------------------------------------------------------------
// Helpers
// ---------------------------------------------------------------------------
__device__ __forceinline__ uint32_t smem_u32(const void* p) {
    return (uint32_t)__cvta_generic_to_shared(p);
}
__device__ __forceinline__ void cp16(uint32_t s, const void* g) {
    asm volatile("cp.async.cg.shared.global [%0], [%1], 16;\n" :: "r"(s), "l"(g));
}
__device__ __forceinline__ void cp_commit() { asm volatile("cp.async.commit_group;\n" ::: "memory"); }
__device__ __forceinline__ void cp_wait0() { asm volatile("cp.async.wait_group 0;\n" ::: "memory"); }
__device__ __forceinline__ void cp_wait1() { asm volatile("cp.async.wait_group 1;\n" ::: "memory"); }

__device__ __forceinline__ void ldm4(uint32_t* r, uint32_t addr) {
    asm volatile("ldmatrix.sync.aligned.m8n8.x4.shared.b16 {%0,%1,%2,%3}, [%4];"
        : "=r"(r[0]), "=r"(r[1]), "=r"(r[2]), "=r"(r[3]) : "r"(addr));
}
__device__ __forceinline__ void mma16816(float* c, const uint32_t* a, const uint32_t* b) {
    asm volatile(
        "mma.sync.aligned.m16n8k16.row.col.f32.bf16.bf16.f32 "
        "{%0,%1,%2,%3}, {%4,%5,%6,%7}, {%8,%9}, {%0,%1,%2,%3};\n"
        : "+f"(c[0]), "+f"(c[1]), "+f"(c[2]), "+f"(c[3])
        : "r"(a[0]), "r"(a[1]), "r"(a[2]), "r"(a[3]), "r"(b[0]), "r"(b[1]));
}

// ---------------------------------------------------------------------------
// K0: W fp32 -> bf16 (rows 0..1023)
// ---------------------------------------------------------------------------
__global__ void k_convW(const float* __restrict__ W) {
    int i = (blockIdx.x * blockDim.x + threadIdx.x) * 2;
    if (i < NPAD * HH) {
        float2 w = *(const float2*)(W + i);
        *(__nv_bfloat162*)(g_Wb + i) = __floats2bfloat162_rn(w.x, w.y);
    }
}

// ---------------------------------------------------------------------------
// K1: A = tanh(enc+dec) -> bf16 scratch, fused GEMV for blank column 1024
// (blank logit written straight into out[row*VV+1024]; k_lsm normalizes it)
// ---------------------------------------------------------------------------
__global__ void __launch_bounds__(256) k_tanhA(
    const float* __restrict__ enc, const float* __restrict__ dec,
    const float* __restrict__ W, const float* __restrict__ bias,
    float* __restrict__ out)
{
    int warp = threadIdx.x >> 5, lane = threadIdx.x & 31;
    int row  = blockIdx.x * 8 + warp;
    int b = row >> 14;
    int t = (row >> 6) & 255;
    int u = row & 63;
    const float* e  = enc + (size_t)(b * TT + t) * HH;
    const float* d  = dec + (size_t)(b * UU + u) * HH;
    const float* wl = W + (size_t)NPAD * HH;   // W[1024,:]
    __nv_bfloat16* arow = g_A + (size_t)row * HH;

    float acc = 0.f;
#pragma unroll
    for (int j = 0; j < 10; j++) {
        int k = j * 64 + lane * 2;
        float2 ev = *(const float2*)(e + k);
        float2 dv = *(const float2*)(d + k);
        float x0 = ev.x + dv.x, x1 = ev.y + dv.y;
        float h0, h1;
        asm("tanh.approx.f32 %0, %1;" : "=f"(h0) : "f"(x0));
        asm("tanh.approx.f32 %0, %1;" : "=f"(h1) : "f"(x1));
        *(__nv_bfloat162*)(arow + k) = __floats2bfloat162_rn(h0, h1);
        float2 wv = *(const float2*)(wl + k);
        acc = fmaf(h0, wv.x, acc);
        acc = fmaf(h1, wv.y, acc);
    }
#pragma unroll
    for (int o = 16; o; o >>= 1) acc += __shfl_xor_sync(0xffffffffu, acc, o);
    if (lane == 0) out[(size_t)row * VV + 1024] = acc + bias[1024];
}

// ---------------------------------------------------------------------------
// K2: GEMM, R14 redesign for tensor-pipe utilization (was 43%):
//  - CTA 128x256 (8 warps, 2Mx4N of 64x64 warp tiles), grid (4,1024), no subs
//  - 3-stage smem ring (55KB/stage, 166KB), prefetch distance 2
//    -> ONE __syncthreads per k-chunk (10 vs 80)
//  - double-buffered register fragments: ks+1's LDSMs issue during ks's HMMAs
//  - cp.async spread: 3 cp16/thread per ks instead of a 12-wide burst
// 1 CTA/SM (smem-bound), 8 warps/SM (same as before), ~220 regs.
// ---------------------------------------------------------------------------
#define PADE 72                  // bf16 per smem row (64 data + 8 pad) = 144B
#define A_BYTES (128*PADE*2)     // 18432
#define B_BYTES (256*PADE*2)     // 36864
#define STG3 (A_BYTES + B_BYTES) // 55296 per stage
#define SMEM_TOTAL (3*STG3)      // 165888

__global__ void __launch_bounds__(256, 1) k_gemm(const float* __restrict__ bias,
                                                 float* __restrict__ out)
{
    extern __shared__ char smem[];
    uint32_t sbase = smem_u32(smem);
    int tid = threadIdx.x;
    int wid = tid >> 5, lane = tid & 31;
    int gid = lane >> 2, tig = lane & 3;
    int la = lane & 7, lb = (lane >> 3) & 1, lc = (lane >> 4) & 1;
    int m0 = blockIdx.y * 128;
    int n0 = blockIdx.x * 256;

    int m_base = (wid & 1) * 64;   // 2 warps along M (64 rows each)
    int n_base = (wid >> 1) * 64;  // 4 warps along N (64 cols each)

    const __nv_bfloat16* Abase = g_A  + (size_t)m0 * HH;
    const __nv_bfloat16* Bbase = g_Wb + (size_t)n0 * HH;

    auto load_stage = [&](int it, int s) {
        uint32_t ab = sbase + s * STG3;
        uint32_t bb = ab + A_BYTES;
        const __nv_bfloat16* Ag = Abase + it * 64;
        const __nv_bfloat16* Bg = Bbase + it * 64;
#pragma unroll
        for (int j = 0; j < 4; j++) {      // A: 128 rows x 8 chunks of 16B
            int c = tid + j * 256;
            int r = c >> 3, cc = c & 7;
            cp16(ab + r * 144 + cc * 16, Ag + (size_t)r * HH + cc * 8);
        }
#pragma unroll
        for (int j = 0; j < 8; j++) {      // B: 256 rows x 8 chunks of 16B
            int c = tid + j * 256;
            int r = c >> 3, cc = c & 7;
            cp16(bb + r * 144 + cc * 16, Bg + (size_t)r * HH + cc * 8);
        }
        cp_commit();
    };

    // ldmatrix per-thread address bases (within a stage)
    uint32_t aAdd = (uint32_t)(m_base + la + lb * 8) * 144 + (uint32_t)lc * 16;
    uint32_t bAdd = (uint32_t)(n_base + la + lc * 8) * 144 + (uint32_t)lb * 16;

    float acc[4][8][4];
#pragma unroll
    for (int mt = 0; mt < 4; mt++)
#pragma unroll
        for (int nt = 0; nt < 8; nt++)
#pragma unroll
            for (int q = 0; q < 4; q++) acc[mt][nt][q] = 0.f;

    load_stage(0, 0);
    load_stage(1, 1);

    for (int g = 0; g < 10; g++) {
        int s = g % 3;
        if (g == 9) cp_wait0(); else cp_wait1();
        __syncthreads();

        uint32_t aB = sbase + s * STG3 + aAdd;
        uint32_t bB = sbase + s * STG3 + A_BYTES + bAdd;

        // prefetch-stage (g+2) parameters
        bool pre = (g + 2 < 10);
        uint32_t s2 = sbase + ((g + 2) % 3) * STG3;
        const __nv_bfloat16* Ag2 = Abase + (g + 2) * 64;
        const __nv_bfloat16* Bg2 = Bbase + (g + 2) * 64;

        // register-fragment double buffer; preload ks=0
        uint32_t a[2][4][4], b[2][8][2];
#pragma unroll
        for (int mt = 0; mt < 4; mt++) ldm4(a[0][mt], aB + mt * 2304);
#pragma unroll
        for (int p = 0; p < 4; p++)    ldm4(&b[0][2 * p][0], bB + p * 2304);

#pragma unroll
        for (int ks = 0; ks < 4; ks++) {
            int cur = ks & 1, nxt = cur ^ 1;
            if (ks < 3) {   // LDSM ks+1 while HMMAs of ks fill the pipe
#pragma unroll
                for (int mt = 0; mt < 4; mt++)
                    ldm4(a[nxt][mt], aB + mt * 2304 + (ks + 1) * 32);
#pragma unroll
                for (int p = 0; p < 4; p++)
                    ldm4(&b[nxt][2 * p][0], bB + p * 2304 + (ks + 1) * 32);
            }
            if (pre) {      // 3 cp16/thread per ks (12 total = full stage)
                int c = tid + ks * 256;
                int r = c >> 3, cc = c & 7;
                cp16(s2 + r * 144 + cc * 16, Ag2 + (size_t)r * HH + cc * 8);
#pragma unroll
                for (int q = 0; q < 2; q++) {
                    int cb = tid + (2 * ks + q) * 256;
                    int rb = cb >> 3, ccb = cb & 7;
                    cp16(s2 + A_BYTES + rb * 144 + ccb * 16,
                         Bg2 + (size_t)rb * HH + ccb * 8);
                }
            }
#pragma unroll
            for (int mt = 0; mt < 4; mt++)
#pragma unroll
                for (int nt = 0; nt < 8; nt++)
                    mma16816(acc[mt][nt], a[cur][mt], b[cur][nt]);
        }
        if (pre) cp_commit();
    }

    // ---- epilogue: bias add + store logits
#pragma unroll
    for (int mt = 0; mt < 4; mt++) {
#pragma unroll
        for (int nt = 0; nt < 8; nt++) {
            int row = m0 + m_base + mt * 16 + gid;
            int col = n0 + n_base + nt * 8 + tig * 2;
            float2 bi = *(const float2*)(bias + col);
            float* p0 = out + (size_t)row * VV + col;
            p0[0] = acc[mt][nt][0] + bi.x;
            p0[1] = acc[mt][nt][1] + bi.y;
            float* p1 = out + (size_t)(row + 8) * VV + col;
            p1[0] = acc[mt][nt][2] + bi.x;
            p1[1] = acc[mt][nt][3] + bi.y;
        }
    }
}

// ---------------------------------------------------------------------------
// K3: in-place log_softmax over last dim (V=1025).
// Warp-per-row: barrier-free, shfl-only reductions, fully-coalesced loads.
// ---------------------------------------------------------------------------
__global__ void __launch_bounds__(256) k_lsm(float* __restrict__ out) {
    int warp = threadIdx.x >> 5, lane = threadIdx.x & 31;
    int row = blockIdx.x * 8 + warp;
    float* p = out + (size_t)row * VV;

    float v[32];
#pragma unroll
    for (int j = 0; j < 32; j++) v[j] = p[lane + j * 32];
    float vb = (lane == 0) ? p[1024] : -1e30f;

    float mx = vb;
#pragma unroll
    for (int j = 0; j < 32; j++) mx = fmaxf(mx, v[j]);
#pragma unroll
    for (int o = 16; o; o >>= 1) mx = fmaxf(mx, __shfl_xor_sync(0xffffffffu, mx, o));

    float s = (lane == 0) ? __expf(vb - mx) : 0.f;
#pragma unroll
    for (int j = 0; j < 32; j++) s += __expf(v[j] - mx);
#pragma unroll
    for (int o = 16; o; o >>= 1) s += __shfl_xor_sync(0xffffffffu, s, o);

    float lse = mx + __logf(s);

#pragma unroll
    for (int j = 0; j < 32; j++) p[lane + j * 32] = v[j] - lse;
    if (lane == 0) p[1024] = vb - lse;
}

// ---------------------------------------------------------------------------
extern "C" void kernel_launch(void* const* d_in, const int* in_sizes, int n_in,
                              void* d_out, int out_size) {
    (void)in_sizes; (void)n_in; (void)out_size;
    const float* enc  = (const float*)d_in[0];
    const float* dec  = (const float*)d_in[1];
    const float* W    = (const float*)d_in[2];
    const float* bias = (const float*)d_in[3];
    float* out = (float*)d_out;

    k_convW<<<(NPAD * HH / 2 + 255) / 256, 256>>>(W);
    k_tanhA<<<NROWS / 8, 256>>>(enc, dec, W, bias, out);

    cudaFuncSetAttribute(k_gemm, cudaFuncAttributeMaxDynamicSharedMemorySize, SMEM_TOTAL);
    dim3 grid(NPAD / 256, NROWS / 128);   // (4, 1024)
    k_gemm<<<grid, 256, SMEM_TOTAL>>>(bias, out);

    k_lsm<<<NROWS / 8, 256>>>(out);
}